// round 15
// baseline (speedup 1.0000x reference)
#include <cuda_runtime.h>
#include <cuda_bf16.h>
#include <math.h>

#define BB   128
#define CH   24
#define PIX  1024
#define D    (CH*PIX)
#define MM   5
#define EPSV 1e-5f
#define LAMV 1e-4f

#define RS    35
#define IN1   (24*34*RS)              // 28560
#define W1L   (64*24*3*4)             // 18432 floats, [ic][ky][oc][4]
#define SMEM1 ((IN1 + W1L)*4)         // 187968 B

#define IN2C  (32*34*RS)              // 38080
#define W2L   (24*32*3*4)             // 9216 floats, [ic][ky][oc][4] (one chunk)
#define SMEM2 ((IN2C + W2L)*4)        // 189184 B

__device__ __forceinline__ void pdl_launch_dependents() {
    asm volatile("griddepcontrol.launch_dependents;");
}
__device__ __forceinline__ void pdl_wait() {
    asm volatile("griddepcontrol.wait;" ::: "memory");
}

// ---------------- device scratch ----------------
__device__ float g_pre [BB*D];
__device__ float g_z   [BB*D];
__device__ float g_F   [MM*BB*D];
__device__ __nv_bfloat16 g_G [MM*BB*D];
__device__ __nv_bfloat16 g_t1[BB*64*PIX];
__device__ float g_H   [BB*MM*MM];
__device__ float g_al  [BB*MM];
__device__ float g_s1  [BB*16];
__device__ float g_acc1[2*CH];
__device__ float g_acc2[2*CH];
__device__ float g_pool[BB*CH*16];

__device__ __forceinline__ uint4 pack8_bf16(const float* v) {
    __nv_bfloat162 h0 = __float22bfloat162_rn(make_float2(v[0], v[1]));
    __nv_bfloat162 h1 = __float22bfloat162_rn(make_float2(v[2], v[3]));
    __nv_bfloat162 h2 = __float22bfloat162_rn(make_float2(v[4], v[5]));
    __nv_bfloat162 h3 = __float22bfloat162_rn(make_float2(v[6], v[7]));
    uint4 u;
    u.x = *(unsigned int*)&h0; u.y = *(unsigned int*)&h1;
    u.z = *(unsigned int*)&h2; u.w = *(unsigned int*)&h3;
    return u;
}
__device__ __forceinline__ void unpack8_bf16(uint4 u, float* v) {
    float2 f0 = __bfloat1622float2(*(__nv_bfloat162*)&u.x);
    float2 f1 = __bfloat1622float2(*(__nv_bfloat162*)&u.y);
    float2 f2 = __bfloat1622float2(*(__nv_bfloat162*)&u.z);
    float2 f3 = __bfloat1622float2(*(__nv_bfloat162*)&u.w);
    v[0]=f0.x; v[1]=f0.y; v[2]=f1.x; v[3]=f1.y;
    v[4]=f2.x; v[5]=f2.y; v[6]=f3.x; v[7]=f3.y;
}

// ---------------- block reduce (sum, sumsq) ----------------
__device__ __forceinline__ void block_reduce_2(float& s, float& s2, float* shm) {
    __syncthreads();
    int lane = threadIdx.x & 31, wid = threadIdx.x >> 5;
#pragma unroll
    for (int o = 16; o > 0; o >>= 1) {
        s  += __shfl_down_sync(0xffffffffu, s,  o);
        s2 += __shfl_down_sync(0xffffffffu, s2, o);
    }
    if (lane == 0) { shm[wid] = s; shm[32 + wid] = s2; }
    __syncthreads();
    int nw = (blockDim.x + 31) >> 5;
    if (wid == 0) {
        s  = (lane < nw) ? shm[lane]      : 0.f;
        s2 = (lane < nw) ? shm[32 + lane] : 0.f;
#pragma unroll
        for (int o = 16; o > 0; o >>= 1) {
            s  += __shfl_down_sync(0xffffffffu, s,  o);
            s2 += __shfl_down_sync(0xffffffffu, s2, o);
        }
        if (lane == 0) { shm[0] = s; shm[32] = s2; }
    }
    __syncthreads();
    s = shm[0]; s2 = shm[32];
}

// ---------------- pre conv 3->24 (+bias) ----------------
__global__ void preconv_kernel(const float* __restrict__ x, const float* __restrict__ w,
                               const float* __restrict__ bias, float* __restrict__ out) {
    __shared__ float s[3*34*34];
    int b = blockIdx.x, tid = threadIdx.x;
    for (int i = tid; i < 3*1156; i += 256) {
        int c = i / 1156, rem = i % 1156, r = rem / 34, cx = rem % 34;
        float v = 0.f;
        if (r >= 1 && r <= 32 && cx >= 1 && cx <= 32)
            v = x[((b*3 + c)*32 + (r-1))*32 + (cx-1)];
        s[i] = v;
    }
    __syncthreads();
    int py = tid >> 3, px0 = (tid & 7) << 2;
    for (int oc0 = 0; oc0 < 24; oc0 += 8) {
        float acc[8][4];
#pragma unroll
        for (int j = 0; j < 8; j++) {
            float bv = __ldg(&bias[oc0 + j]);
#pragma unroll
            for (int p = 0; p < 4; p++) acc[j][p] = bv;
        }
        for (int ic = 0; ic < 3; ic++)
#pragma unroll
            for (int ky = 0; ky < 3; ky++) {
                const float* row = &s[ic*1156 + (py + ky)*34 + px0];
                float r0=row[0],r1=row[1],r2=row[2],r3=row[3],r4=row[4],r5=row[5];
#pragma unroll
                for (int j = 0; j < 8; j++) {
                    int oc = oc0 + j;
                    const float* wq = &w[((oc*3 + ic)*3 + ky)*3];
                    float w0=__ldg(wq), w1=__ldg(wq+1), w2=__ldg(wq+2);
                    acc[j][0] += r0*w0 + r1*w1 + r2*w2;
                    acc[j][1] += r1*w0 + r2*w1 + r3*w2;
                    acc[j][2] += r2*w0 + r3*w1 + r4*w2;
                    acc[j][3] += r3*w0 + r4*w1 + r5*w2;
                }
            }
#pragma unroll
        for (int j = 0; j < 8; j++)
#pragma unroll
            for (int p = 0; p < 4; p++)
                out[(b*24 + oc0 + j)*PIX + py*32 + px0 + p] = acc[j][p];
    }
}

// ---------------- BN accumulate: grid (24, 8), atomics into acc[2*CH] ----------------
__global__ void bn_acc_kernel(const float* __restrict__ in, float* __restrict__ acc,
                              int relu_flag) {
    __shared__ float shm[64];
    int c = blockIdx.x, sl = blockIdx.y;
    float s = 0.f, s2 = 0.f;
    for (int i = threadIdx.x; i < 16*PIX; i += blockDim.x) {
        int b = sl*16 + (i >> 10), p = i & 1023;
        float v = in[(b*CH + c)*PIX + p];
        if (relu_flag) v = fmaxf(v, 0.f);
        s += v; s2 += v*v;
    }
    block_reduce_2(s, s2, shm);
    if (threadIdx.x == 0) {
        atomicAdd(&acc[c], s);
        atomicAdd(&acc[CH + c], s2);
    }
}

// ---------------- conv1: 24->64 3x3 SAME + relu + gn1 stats (t1 bf16)
//   combine mode: z = sum(alpha_i F_i) computed on the fly, written to zout ----------------
__global__ void __launch_bounds__(512, 1)
conv1_kernel(const float* __restrict__ z, const float* __restrict__ Fb,
             const float* __restrict__ al, float* __restrict__ zout, int z_zero,
             const float* __restrict__ w, __nv_bfloat16* __restrict__ t1,
             float* __restrict__ s1o) {
    extern __shared__ float s[];
    float* ws = s + IN1;
    __shared__ float gs[8], gq[8];
    int b = blockIdx.x, tid = threadIdx.x;
    const size_t SLOT = (size_t)BB * D;
    pdl_launch_dependents();
    if (tid < 8) { gs[tid] = 0.f; gq[tid] = 0.f; }
    {
        float4 z4; z4.x=0.f; z4.y=0.f; z4.z=0.f; z4.w=0.f;
        float4* s4 = (float4*)s;
        for (int i = tid; i < IN1/4; i += 512) s4[i] = z4;
    }
    for (int i = tid; i < 64*24*3; i += 512) {
        int oc = i / 72, rem = i % 72, ic = rem / 3, ky = rem % 3;
        const float* src = w + (oc*24 + ic)*9 + ky*3;
        float* dst = ws + ((ic*3 + ky)*64 + oc)*4;
        dst[0] = src[0]; dst[1] = src[1]; dst[2] = src[2]; dst[3] = 0.f;
    }
    pdl_wait();
    __syncthreads();
    if (zout) {
        float a0=al[b*5+0], a1=al[b*5+1], a2=al[b*5+2], a3=al[b*5+3], a4=al[b*5+4];
        for (int task = tid; task < 768; task += 512) {
            int c = task >> 5, gr = task & 31;
            size_t off = (size_t)(b*24 + c)*PIX + gr*32;
            const float4* f0 = (const float4*)(Fb + off);
            const float4* f1 = (const float4*)(Fb + off + SLOT);
            const float4* f2 = (const float4*)(Fb + off + 2*SLOT);
            const float4* f3 = (const float4*)(Fb + off + 3*SLOT);
            const float4* f4 = (const float4*)(Fb + off + 4*SLOT);
            float4* zo = (float4*)(zout + off);
            float* dst = &s[c*(34*RS) + (gr+1)*RS + 1];
#pragma unroll
            for (int q = 0; q < 8; q++) {
                float4 v0=f0[q], v1=f1[q], v2=f2[q], v3=f3[q], v4=f4[q];
                float4 r;
                r.x = a0*v0.x + a1*v1.x + a2*v2.x + a3*v3.x + a4*v4.x;
                r.y = a0*v0.y + a1*v1.y + a2*v2.y + a3*v3.y + a4*v4.y;
                r.z = a0*v0.z + a1*v1.z + a2*v2.z + a3*v3.z + a4*v4.z;
                r.w = a0*v0.w + a1*v1.w + a2*v2.w + a3*v3.w + a4*v4.w;
                zo[q] = r;
                dst[q*4+0]=r.x; dst[q*4+1]=r.y; dst[q*4+2]=r.z; dst[q*4+3]=r.w;
            }
        }
    } else if (!z_zero) {
        for (int task = tid; task < 768; task += 512) {
            int c = task >> 5, gr = task & 31;
            size_t off = (size_t)(b*24 + c)*PIX + gr*32;
            const float4* zp = (const float4*)(z + off);
            float* dst = &s[c*(34*RS) + (gr+1)*RS + 1];
#pragma unroll
            for (int q = 0; q < 8; q++) {
                float4 v = zp[q];
                dst[q*4+0]=v.x; dst[q*4+1]=v.y; dst[q*4+2]=v.z; dst[q*4+3]=v.w;
            }
        }
    }
    __syncthreads();
    int ocg = tid >> 7;
    int t = tid & 127;
    int py = t >> 2, px0 = (t & 3) << 3;
    int lane = tid & 31;
#pragma unroll 1
    for (int tile = 0; tile < 2; tile++) {
        int oc0 = tile*32 + ocg*8;
        float acc[8][8];
#pragma unroll
        for (int j = 0; j < 8; j++)
#pragma unroll
            for (int p = 0; p < 8; p++) acc[j][p] = 0.f;
#pragma unroll 1
        for (int ic = 0; ic < 24; ic++)
#pragma unroll
            for (int ky = 0; ky < 3; ky++) {
                const float* row = &s[ic*(34*RS) + (py + ky)*RS + px0];
                float r[10];
#pragma unroll
                for (int p = 0; p < 10; p++) r[p] = row[p];
                const float4* wq4 = (const float4*)&ws[((ic*3 + ky)*64 + oc0)*4];
#pragma unroll
                for (int j = 0; j < 8; j++) {
                    float4 wv = wq4[j];
#pragma unroll
                    for (int p = 0; p < 8; p++)
                        acc[j][p] += r[p]*wv.x + r[p+1]*wv.y + r[p+2]*wv.z;
                }
            }
        float ss = 0.f, qq = 0.f;
#pragma unroll
        for (int j = 0; j < 8; j++) {
            float v[8];
#pragma unroll
            for (int p = 0; p < 8; p++) {
                v[p] = fmaxf(acc[j][p], 0.f);
                ss += v[p]; qq += v[p]*v[p];
            }
            *(uint4*)&t1[(size_t)(b*64 + oc0 + j)*PIX + py*32 + px0] = pack8_bf16(v);
        }
#pragma unroll
        for (int o = 16; o > 0; o >>= 1) {
            ss += __shfl_down_sync(0xffffffffu, ss, o);
            qq += __shfl_down_sync(0xffffffffu, qq, o);
        }
        if (lane == 0) {
            int grp = oc0 >> 3;
            atomicAdd(&gs[grp], ss);
            atomicAdd(&gq[grp], qq);
        }
    }
    __syncthreads();
    if (tid < 8) {
        float m = gs[tid] * (1.f/8192.f);
        float var = gq[tid] * (1.f/8192.f) - m*m;
        s1o[b*16 + tid*2]     = m;
        s1o[b*16 + tid*2 + 1] = rsqrtf(var + EPSV);
    }
}

// ---------------- conv2f: gn1-affine load (bf16 t1), conv 64->24 + BN(pre) inline,
//   gn2 -> +z -> relu -> gn3; writes F; if do_gram: G, Gram row slt, next alpha ----------------
__global__ void __launch_bounds__(512, 1)
conv2f_kernel(const __nv_bfloat16* __restrict__ t1, const float* __restrict__ w,
              const float* __restrict__ s1, const float* __restrict__ g1g,
              const float* __restrict__ g1b,
              const float* __restrict__ pre, const float* __restrict__ ac1,
              const float* __restrict__ pbng, const float* __restrict__ pbnb,
              const float* __restrict__ zin, int z_zero,
              const float* __restrict__ g2g, const float* __restrict__ b2g,
              const float* __restrict__ g3g, const float* __restrict__ b3g,
              float* __restrict__ Fout, __nv_bfloat16* __restrict__ Gbuf,
              const __nv_bfloat16* __restrict__ Gall, int slt, float* __restrict__ Hb,
              int next_n, float* __restrict__ alpha, int do_gram) {
    extern __shared__ float s[];
    float* ws = s + IN2C;
    __shared__ float sc[64], bs[64];
    __shared__ float pxs[CH], pxb[CH];
    __shared__ float gs2[8], gq2[8], gs3[8], gq3[8];
    __shared__ float st2[16], st3[16];
    __shared__ float hd[MM];
    __shared__ float c2s[CH], c2b[CH], c3s[CH], c3b[CH];
    int b = blockIdx.x, tid = threadIdx.x;
    const size_t SLOT = (size_t)BB * D;
    pdl_launch_dependents();
    if (tid >= 64 && tid < 72) { gs2[tid-64]=0.f; gq2[tid-64]=0.f; gs3[tid-64]=0.f; gq3[tid-64]=0.f; }
    if (tid >= 96 && tid < 96+CH) {
        int c = tid - 96;
        c2s[c] = g2g[c]; c2b[c] = b2g[c];
        c3s[c] = g3g[c]; c3b[c] = b3g[c];
    }
    if (tid >= 128 && tid < 128+MM) hd[tid-128] = 0.f;
    {
        float4 z4; z4.x=0.f; z4.y=0.f; z4.z=0.f; z4.w=0.f;
        float4* s4 = (float4*)s;
        for (int i = tid; i < IN2C/4; i += 512) s4[i] = z4;
    }
    // chunk 0 weights repacked pre-wait
    for (int i = tid; i < 24*32*3; i += 512) {
        int oc = i / 96, rem = i % 96, ic = rem / 3, ky = rem % 3;
        const float* src = w + (oc*64 + ic)*9 + ky*3;
        float* dst = ws + ((ic*3 + ky)*24 + oc)*4;
        dst[0] = src[0]; dst[1] = src[1]; dst[2] = src[2]; dst[3] = 0.f;
    }
    pdl_wait();
    if (tid < 64) {
        int grp = tid >> 3;
        float m = s1[b*16 + grp*2], rs = s1[b*16 + grp*2 + 1];
        float gam = g1g[tid];
        sc[tid] = rs * gam;
        bs[tid] = g1b[tid] - m * rs * gam;
    }
    if (tid >= 448 && tid < 448+CH) {
        int c = tid - 448;
        float m = ac1[c] * (1.f/(BB*PIX));
        float rs = rsqrtf(ac1[CH + c] * (1.f/(BB*PIX)) - m*m + EPSV);
        float sgl = rs * pbng[c];
        pxs[c] = sgl;
        pxb[c] = pbnb[c] - m * sgl;
    }
    int ocg = tid >> 7, t = tid & 127;
    int py = t >> 2, px0 = (t & 3) << 3;
    int lane = tid & 31;
    float acc[6][8];
#pragma unroll
    for (int j = 0; j < 6; j++)
#pragma unroll
        for (int p = 0; p < 8; p++) acc[j][p] = 0.f;
#pragma unroll 1
    for (int chunk = 0; chunk < 2; chunk++) {
        __syncthreads();
        int icb = chunk * 32;
        if (chunk == 1) {
            for (int i = tid; i < 24*32*3; i += 512) {
                int oc = i / 96, rem = i % 96, ic = rem / 3, ky = rem % 3;
                const float* src = w + (oc*64 + 32 + ic)*9 + ky*3;
                float* dst = ws + ((ic*3 + ky)*24 + oc)*4;
                dst[0] = src[0]; dst[1] = src[1]; dst[2] = src[2]; dst[3] = 0.f;
            }
        }
        for (int task = tid; task < 1024; task += 512) {
            int c = task >> 5, gr = task & 31;
            int cg = icb + c;
            float scv = sc[cg], bsv = bs[cg];
            const uint4* tp = (const uint4*)(t1 + (size_t)(b*64 + cg)*PIX + gr*32);
            float* dst = &s[c*(34*RS) + (gr+1)*RS + 1];
#pragma unroll
            for (int q = 0; q < 4; q++) {
                float v[8];
                unpack8_bf16(tp[q], v);
#pragma unroll
                for (int e = 0; e < 8; e++)
                    dst[q*8 + e] = v[e]*scv + bsv;
            }
        }
        __syncthreads();
#pragma unroll 1
        for (int ic = 0; ic < 32; ic++)
#pragma unroll
            for (int ky = 0; ky < 3; ky++) {
                const float* row = &s[ic*(34*RS) + (py + ky)*RS + px0];
                float r[10];
#pragma unroll
                for (int p = 0; p < 10; p++) r[p] = row[p];
                const float4* wq4 = (const float4*)&ws[((ic*3 + ky)*24 + ocg*6)*4];
#pragma unroll
                for (int j = 0; j < 6; j++) {
                    float4 wv = wq4[j];
#pragma unroll
                    for (int p = 0; p < 8; p++)
                        acc[j][p] += r[p]*wv.x + r[p+1]*wv.y + r[p+2]*wv.z;
                }
            }
    }
    // ---- v = conv + BN(pre) inline ; gn2 stats ----
    float ss[2] = {0.f, 0.f}, qq[2] = {0.f, 0.f};
#pragma unroll
    for (int j = 0; j < 6; j++) {
        int c = ocg*6 + j;
        float ps = pxs[c], pb = pxb[c];
        size_t idx = (size_t)(b*24 + c)*PIX + py*32 + px0;
        float4 x0 = *(const float4*)&pre[idx];
        float4 x1 = *(const float4*)&pre[idx + 4];
        acc[j][0] += x0.x*ps + pb; acc[j][1] += x0.y*ps + pb;
        acc[j][2] += x0.z*ps + pb; acc[j][3] += x0.w*ps + pb;
        acc[j][4] += x1.x*ps + pb; acc[j][5] += x1.y*ps + pb;
        acc[j][6] += x1.z*ps + pb; acc[j][7] += x1.w*ps + pb;
        int u = j / 3;
        float sv = 0.f, qv = 0.f;
#pragma unroll
        for (int p = 0; p < 8; p++) { sv += acc[j][p]; qv += acc[j][p]*acc[j][p]; }
        ss[u] += sv; qq[u] += qv;
    }
#pragma unroll
    for (int o = 16; o > 0; o >>= 1)
#pragma unroll
        for (int u = 0; u < 2; u++) {
            ss[u] += __shfl_down_sync(0xffffffffu, ss[u], o);
            qq[u] += __shfl_down_sync(0xffffffffu, qq[u], o);
        }
    if (lane == 0)
#pragma unroll
        for (int u = 0; u < 2; u++) {
            atomicAdd(&gs2[ocg*2 + u], ss[u]);
            atomicAdd(&gq2[ocg*2 + u], qq[u]);
        }
    __syncthreads();
    if (tid < 8) {
        float m = gs2[tid] * (1.f/3072.f);
        st2[tid*2]   = m;
        st2[tid*2+1] = rsqrtf(gq2[tid] * (1.f/3072.f) - m*m + EPSV);
    }
    __syncthreads();
    // ---- w = relu(z + gn2affine(v)) ; gn3 stats ; cache z in smem ----
    float s3[2] = {0.f, 0.f}, q3[2] = {0.f, 0.f};
#pragma unroll
    for (int j = 0; j < 6; j++) {
        int c = ocg*6 + j;
        int grp = c / 3;
        float m1 = st2[grp*2], rs1 = st2[grp*2+1];
        float scl = rs1 * c2s[c];
        float off = c2b[c] - m1 * scl;
        size_t idx = (size_t)(b*24 + c)*PIX + py*32 + px0;
        float zv[8];
        if (z_zero) {
#pragma unroll
            for (int p = 0; p < 8; p++) zv[p] = 0.f;
        } else {
            float4 z0 = *(const float4*)&zin[idx];
            float4 z1 = *(const float4*)&zin[idx + 4];
            zv[0]=z0.x; zv[1]=z0.y; zv[2]=z0.z; zv[3]=z0.w;
            zv[4]=z1.x; zv[5]=z1.y; zv[6]=z1.z; zv[7]=z1.w;
        }
        float* zs = &s[c*PIX + py*32 + px0];
        *(float4*)zs = make_float4(zv[0], zv[1], zv[2], zv[3]);
        *(float4*)(zs + 4) = make_float4(zv[4], zv[5], zv[6], zv[7]);
        int u = j / 3;
        float sv = 0.f, qv = 0.f;
#pragma unroll
        for (int p = 0; p < 8; p++) {
            float wv = fmaxf(zv[p] + acc[j][p]*scl + off, 0.f);
            acc[j][p] = wv;
            sv += wv; qv += wv*wv;
        }
        s3[u] += sv; q3[u] += qv;
    }
#pragma unroll
    for (int o = 16; o > 0; o >>= 1)
#pragma unroll
        for (int u = 0; u < 2; u++) {
            s3[u] += __shfl_down_sync(0xffffffffu, s3[u], o);
            q3[u] += __shfl_down_sync(0xffffffffu, q3[u], o);
        }
    if (lane == 0)
#pragma unroll
        for (int u = 0; u < 2; u++) {
            atomicAdd(&gs3[ocg*2 + u], s3[u]);
            atomicAdd(&gq3[ocg*2 + u], q3[u]);
        }
    __syncthreads();
    if (tid < 8) {
        float m = gs3[tid] * (1.f/3072.f);
        st3[tid*2]   = m;
        st3[tid*2+1] = rsqrtf(gq3[tid] * (1.f/3072.f) - m*m + EPSV);
    }
    __syncthreads();
    // ---- F = gn3affine(w); optionally G = F - z (bf16) + Gram row slt (z from smem) ----
    float dot[MM];
#pragma unroll
    for (int i = 0; i < MM; i++) dot[i] = 0.f;
#pragma unroll
    for (int j = 0; j < 6; j++) {
        int c = ocg*6 + j;
        int grp = c / 3;
        float m2 = st3[grp*2], rs2 = st3[grp*2+1];
        float scl = rs2 * c3s[c];
        float off = c3b[c] - m2 * scl;
        size_t idx = (size_t)(b*24 + c)*PIX + py*32 + px0;
        const float* zs = &s[c*PIX + py*32 + px0];
        float4 z0 = *(const float4*)zs;
        float4 z1 = *(const float4*)(zs + 4);
        float zv[8] = {z0.x,z0.y,z0.z,z0.w,z1.x,z1.y,z1.z,z1.w};
        float fv[8], gv[8];
#pragma unroll
        for (int p = 0; p < 8; p++) {
            fv[p] = acc[j][p]*scl + off;
            gv[p] = fv[p] - zv[p];
        }
        float4 f0; f0.x=fv[0]; f0.y=fv[1]; f0.z=fv[2]; f0.w=fv[3];
        float4 f1; f1.x=fv[4]; f1.y=fv[5]; f1.z=fv[6]; f1.w=fv[7];
        *(float4*)&Fout[idx] = f0; *(float4*)&Fout[idx + 4] = f1;
        if (do_gram) {
            *(uint4*)&Gbuf[idx] = pack8_bf16(gv);
#pragma unroll
            for (int i = 0; i < MM; i++) {
                if (i == slt) {
#pragma unroll
                    for (int p = 0; p < 8; p++) dot[i] += gv[p]*gv[p];
                } else {
                    uint4 u = *(const uint4*)(Gall + (size_t)i * SLOT + idx);
                    float gi[8];
                    unpack8_bf16(u, gi);
#pragma unroll
                    for (int p = 0; p < 8; p++) dot[i] += gv[p]*gi[p];
                }
            }
        }
    }
    if (do_gram) {
#pragma unroll
        for (int o = 16; o > 0; o >>= 1)
#pragma unroll
            for (int i = 0; i < MM; i++)
                dot[i] += __shfl_down_sync(0xffffffffu, dot[i], o);
        if (lane == 0)
#pragma unroll
            for (int i = 0; i < MM; i++) atomicAdd(&hd[i], dot[i]);
        __syncthreads();
        if (tid < MM) {
            float v = hd[tid];
            Hb[b*25 + slt*5 + tid] = v;
            Hb[b*25 + tid*5 + slt] = v;
        }
        __syncthreads();
        if (next_n > 0 && tid == 0) {
            int n = next_n, m = n + 1;
            float A[6][7];
            for (int i = 0; i < m; i++)
                for (int j = 0; j <= m; j++) A[i][j] = 0.f;
            for (int j = 1; j < m; j++) { A[0][j] = 1.f; A[j][0] = 1.f; }
            for (int i = 0; i < n; i++)
                for (int j = 0; j < n; j++) {
                    float hij = (i == slt) ? hd[j] : ((j == slt) ? hd[i] : Hb[b*25 + i*5 + j]);
                    A[i+1][j+1] = hij + ((i == j) ? LAMV : 0.f);
                }
            A[0][m] = 1.f;
            for (int col = 0; col < m; col++) {
                int piv = col; float best = fabsf(A[col][col]);
                for (int r = col + 1; r < m; r++) {
                    float v = fabsf(A[r][col]);
                    if (v > best) { best = v; piv = r; }
                }
                if (piv != col)
                    for (int j = col; j <= m; j++) { float tv = A[col][j]; A[col][j] = A[piv][j]; A[piv][j] = tv; }
                float inv = 1.f / A[col][col];
                for (int r = col + 1; r < m; r++) {
                    float f = A[r][col] * inv;
                    for (int j = col; j <= m; j++) A[r][j] -= f * A[col][j];
                }
            }
            float xs[6];
            for (int i = m - 1; i >= 0; i--) {
                float v = A[i][m];
                for (int j = i + 1; j < m; j++) v -= A[i][j] * xs[j];
                xs[i] = v / A[i][i];
            }
            for (int i = 0; i < 5; i++) alpha[b*5 + i] = (i < n) ? xs[i + 1] : 0.f;
        }
    }
}

// ---------------- post: relu -> BN apply (inline stats) -> 8x8 avgpool ----------------
__global__ void pool_kernel(const float* __restrict__ z, const float* __restrict__ acc,
                            const float* __restrict__ g, const float* __restrict__ bta,
                            float* __restrict__ pooled) {
    __shared__ float pl[16];
    __shared__ float smc, src_;
    int b = blockIdx.x / 24, c = blockIdx.x % 24;
    if (threadIdx.x < 16) pl[threadIdx.x] = 0.f;
    if (threadIdx.x == 0) {
        float m = acc[c] * (1.f/(BB*PIX));
        float var = acc[CH + c] * (1.f/(BB*PIX)) - m*m;
        smc = m; src_ = rsqrtf(var + EPSV);
    }
    __syncthreads();
    float mc = smc, rc = src_, gc = g[c], bc = bta[c];
    for (int i = threadIdx.x; i < 1024; i += 256) {
        int yy = i >> 5, xx = i & 31;
        float v = fmaxf(z[(b*24 + c)*PIX + i], 0.f);
        v = (v - mc) * rc * gc + bc;
        atomicAdd(&pl[(yy >> 3)*4 + (xx >> 3)], v);
    }
    __syncthreads();
    if (threadIdx.x < 16)
        pooled[(b*24 + c)*16 + threadIdx.x] = pl[threadIdx.x] * (1.f/64.f);
}

// ---------------- final FC ----------------
__global__ void fc_kernel(const float* __restrict__ pooled, const float* __restrict__ w,
                          const float* __restrict__ bias, float* __restrict__ out) {
    int b = blockIdx.x;
    int warp = threadIdx.x >> 5, lane = threadIdx.x & 31;
    float acc = 0.f;
    for (int k = lane; k < 384; k += 32)
        acc += pooled[b*384 + k] * w[warp*384 + k];
#pragma unroll
    for (int o = 16; o > 0; o >>= 1) acc += __shfl_down_sync(0xffffffffu, acc, o);
    if (lane == 0) out[b*10 + warp] = acc + bias[warp];
}

// ---------------- host orchestration ----------------
extern "C" void kernel_launch(void* const* d_in, const int* in_sizes, int n_in,
                              void* d_out, int out_size) {
    const float* x     = (const float*)d_in[0];
    const float* pw    = (const float*)d_in[1];
    const float* pbia  = (const float*)d_in[2];
    const float* pbn_g = (const float*)d_in[3];
    const float* pbn_b = (const float*)d_in[4];
    const float* w1    = (const float*)d_in[5];
    const float* g1g   = (const float*)d_in[6];
    const float* g1b   = (const float*)d_in[7];
    const float* w2    = (const float*)d_in[8];
    const float* g2g   = (const float*)d_in[9];
    const float* g2b   = (const float*)d_in[10];
    const float* g3g   = (const float*)d_in[11];
    const float* g3b   = (const float*)d_in[12];
    const float* qbn_g = (const float*)d_in[13];
    const float* qbn_b = (const float*)d_in[14];
    const float* fcw   = (const float*)d_in[15];
    const float* fcb   = (const float*)d_in[16];
    float* out = (float*)d_out;

    static bool attr_done = false;
    if (!attr_done) {
        cudaFuncSetAttribute(conv1_kernel,  cudaFuncAttributeMaxDynamicSharedMemorySize, SMEM1);
        cudaFuncSetAttribute(conv2f_kernel, cudaFuncAttributeMaxDynamicSharedMemorySize, SMEM2);
        attr_done = true;
    }

    float *zb, *Fb, *pre, *Hb, *al, *s1, *ac1, *ac2, *pl;
    __nv_bfloat16 *Gb, *t1;
    cudaGetSymbolAddress((void**)&zb,  g_z);
    cudaGetSymbolAddress((void**)&Fb,  g_F);
    cudaGetSymbolAddress((void**)&Gb,  g_G);
    cudaGetSymbolAddress((void**)&pre, g_pre);
    cudaGetSymbolAddress((void**)&t1,  g_t1);
    cudaGetSymbolAddress((void**)&Hb,  g_H);
    cudaGetSymbolAddress((void**)&al,  g_al);
    cudaGetSymbolAddress((void**)&s1,  g_s1);
    cudaGetSymbolAddress((void**)&ac1, g_acc1);
    cudaGetSymbolAddress((void**)&ac2, g_acc2);
    cudaGetSymbolAddress((void**)&pl,  g_pool);

    const size_t SLOT = (size_t)BB * D;

    cudaMemsetAsync(ac1, 0, 2*CH*sizeof(float));
    cudaMemsetAsync(ac2, 0, 2*CH*sizeof(float));

    preconv_kernel<<<128, 256>>>(x, pw, pbia, pre);
    bn_acc_kernel<<<dim3(24, 8), 256>>>(pre, ac1, 0);

    cudaLaunchAttribute pdl_attr[1];
    pdl_attr[0].id = cudaLaunchAttributeProgrammaticStreamSerialization;
    pdl_attr[0].val.programmaticStreamSerializationAllowed = 1;

    auto launch_conv1 = [&](const float* zptr, bool combine, int z_zero) {
        cudaLaunchConfig_t cfg = {};
        cfg.gridDim = dim3(128, 1, 1);
        cfg.blockDim = dim3(512, 1, 1);
        cfg.dynamicSmemBytes = SMEM1;
        cfg.stream = 0;
        cfg.attrs = pdl_attr;
        cfg.numAttrs = 1;
        cudaLaunchKernelEx(&cfg, conv1_kernel,
                           zptr, (const float*)Fb, (const float*)al,
                           combine ? zb : (float*)nullptr, z_zero,
                           w1, t1, s1);
    };
    auto launch_conv2f = [&](const float* zptr, int z_zero, int slt, int next_n, int do_gram) {
        cudaLaunchConfig_t cfg = {};
        cfg.gridDim = dim3(128, 1, 1);
        cfg.blockDim = dim3(512, 1, 1);
        cfg.dynamicSmemBytes = SMEM2;
        cfg.stream = 0;
        cfg.attrs = pdl_attr;
        cfg.numAttrs = 1;
        cudaLaunchKernelEx(&cfg, conv2f_kernel,
                           (const __nv_bfloat16*)t1, w2, (const float*)s1, g1g, g1b,
                           (const float*)pre, (const float*)ac1, pbn_g, pbn_b,
                           zptr, z_zero,
                           g2g, g2b, g3g, g3b,
                           Fb + (size_t)slt*SLOT, Gb + (size_t)slt*SLOT,
                           (const __nv_bfloat16*)Gb, slt, Hb, next_n, al, do_gram);
    };

    // iter 0: z = 0  ->  F0 (slot 0)
    launch_conv1(nullptr, false, 1);
    launch_conv2f(nullptr, 1, 0, 0, 1);
    // iter 1: z = F0 (read in place)  ->  F1 (slot 1); alpha for k=2
    launch_conv1(Fb, false, 0);
    launch_conv2f(Fb, 0, 1, 2, 1);

    for (int k = 2; k < 25; k++) {
        int nn = (k + 1 < 5) ? (k + 1) : 5;
        launch_conv1(zb, true, 0);                       // conv1 builds z into zb
        launch_conv2f(zb, 0, k % 5, (k < 24) ? nn : 0, (k < 24) ? 1 : 0);
    }

    const float* zf = Fb + 4 * SLOT;   // z = f(z_star) = F[:,4]

    bn_acc_kernel<<<dim3(24, 8), 256>>>(zf, ac2, 1);
    pool_kernel<<<128*24, 256>>>(zf, ac2, qbn_g, qbn_b, pl);
    fc_kernel<<<128, 320>>>(pl, fcw, fcb, out);
}

// round 16
// speedup vs baseline: 1.0071x; 1.0071x over previous
#include <cuda_runtime.h>
#include <cuda_bf16.h>
#include <math.h>

#define BB   128
#define CH   24
#define PIX  1024
#define D    (CH*PIX)
#define MM   5
#define EPSV 1e-5f
#define LAMV 1e-4f

#define RS    35
#define IN1   (24*34*RS)              // 28560
#define W1L   (64*24*3*4)             // 18432 floats, [ic][ky][oc][4]
#define SMEM1 ((IN1 + W1L)*4)         // 187968 B

#define IN2C  (32*34*RS)              // 38080
#define W2L   (24*32*3*4)             // 9216 floats, [ic][ky][oc][4] (one chunk)
#define SMEM2 ((IN2C + W2L)*4)        // 189184 B

__device__ __forceinline__ void pdl_launch_dependents() {
    asm volatile("griddepcontrol.launch_dependents;");
}
__device__ __forceinline__ void pdl_wait() {
    asm volatile("griddepcontrol.wait;" ::: "memory");
}

// ---------------- device scratch ----------------
__device__ float g_pre [BB*D];
__device__ float g_xp  [BB*D];
__device__ float g_z   [BB*D];
__device__ float g_F   [MM*BB*D];
__device__ __nv_bfloat16 g_G [MM*BB*D];
__device__ __nv_bfloat16 g_t1[BB*64*PIX];
__device__ float g_H   [BB*MM*MM];
__device__ float g_al  [BB*MM];
__device__ float g_s1  [BB*16];
__device__ float g_acc1[2*CH];
__device__ float g_acc2[2*CH];
__device__ float g_pool[BB*CH*16];

__device__ __forceinline__ uint4 pack8_bf16(const float* v) {
    __nv_bfloat162 h0 = __float22bfloat162_rn(make_float2(v[0], v[1]));
    __nv_bfloat162 h1 = __float22bfloat162_rn(make_float2(v[2], v[3]));
    __nv_bfloat162 h2 = __float22bfloat162_rn(make_float2(v[4], v[5]));
    __nv_bfloat162 h3 = __float22bfloat162_rn(make_float2(v[6], v[7]));
    uint4 u;
    u.x = *(unsigned int*)&h0; u.y = *(unsigned int*)&h1;
    u.z = *(unsigned int*)&h2; u.w = *(unsigned int*)&h3;
    return u;
}
__device__ __forceinline__ void unpack8_bf16(uint4 u, float* v) {
    float2 f0 = __bfloat1622float2(*(__nv_bfloat162*)&u.x);
    float2 f1 = __bfloat1622float2(*(__nv_bfloat162*)&u.y);
    float2 f2 = __bfloat1622float2(*(__nv_bfloat162*)&u.z);
    float2 f3 = __bfloat1622float2(*(__nv_bfloat162*)&u.w);
    v[0]=f0.x; v[1]=f0.y; v[2]=f1.x; v[3]=f1.y;
    v[4]=f2.x; v[5]=f2.y; v[6]=f3.x; v[7]=f3.y;
}

// ---------------- block reduce (sum, sumsq) ----------------
__device__ __forceinline__ void block_reduce_2(float& s, float& s2, float* shm) {
    __syncthreads();
    int lane = threadIdx.x & 31, wid = threadIdx.x >> 5;
#pragma unroll
    for (int o = 16; o > 0; o >>= 1) {
        s  += __shfl_down_sync(0xffffffffu, s,  o);
        s2 += __shfl_down_sync(0xffffffffu, s2, o);
    }
    if (lane == 0) { shm[wid] = s; shm[32 + wid] = s2; }
    __syncthreads();
    int nw = (blockDim.x + 31) >> 5;
    if (wid == 0) {
        s  = (lane < nw) ? shm[lane]      : 0.f;
        s2 = (lane < nw) ? shm[32 + lane] : 0.f;
#pragma unroll
        for (int o = 16; o > 0; o >>= 1) {
            s  += __shfl_down_sync(0xffffffffu, s,  o);
            s2 += __shfl_down_sync(0xffffffffu, s2, o);
        }
        if (lane == 0) { shm[0] = s; shm[32] = s2; }
    }
    __syncthreads();
    s = shm[0]; s2 = shm[32];
}

// ---------------- pre conv 3->24 (+bias) ----------------
__global__ void preconv_kernel(const float* __restrict__ x, const float* __restrict__ w,
                               const float* __restrict__ bias, float* __restrict__ out) {
    __shared__ float s[3*34*34];
    int b = blockIdx.x, tid = threadIdx.x;
    for (int i = tid; i < 3*1156; i += 256) {
        int c = i / 1156, rem = i % 1156, r = rem / 34, cx = rem % 34;
        float v = 0.f;
        if (r >= 1 && r <= 32 && cx >= 1 && cx <= 32)
            v = x[((b*3 + c)*32 + (r-1))*32 + (cx-1)];
        s[i] = v;
    }
    __syncthreads();
    int py = tid >> 3, px0 = (tid & 7) << 2;
    for (int oc0 = 0; oc0 < 24; oc0 += 8) {
        float acc[8][4];
#pragma unroll
        for (int j = 0; j < 8; j++) {
            float bv = __ldg(&bias[oc0 + j]);
#pragma unroll
            for (int p = 0; p < 4; p++) acc[j][p] = bv;
        }
        for (int ic = 0; ic < 3; ic++)
#pragma unroll
            for (int ky = 0; ky < 3; ky++) {
                const float* row = &s[ic*1156 + (py + ky)*34 + px0];
                float r0=row[0],r1=row[1],r2=row[2],r3=row[3],r4=row[4],r5=row[5];
#pragma unroll
                for (int j = 0; j < 8; j++) {
                    int oc = oc0 + j;
                    const float* wq = &w[((oc*3 + ic)*3 + ky)*3];
                    float w0=__ldg(wq), w1=__ldg(wq+1), w2=__ldg(wq+2);
                    acc[j][0] += r0*w0 + r1*w1 + r2*w2;
                    acc[j][1] += r1*w0 + r2*w1 + r3*w2;
                    acc[j][2] += r2*w0 + r3*w1 + r4*w2;
                    acc[j][3] += r3*w0 + r4*w1 + r5*w2;
                }
            }
#pragma unroll
        for (int j = 0; j < 8; j++)
#pragma unroll
            for (int p = 0; p < 4; p++)
                out[(b*24 + oc0 + j)*PIX + py*32 + px0 + p] = acc[j][p];
    }
}

// ---------------- BN accumulate: grid (24, 8), atomics into acc[2*CH] ----------------
__global__ void bn_acc_kernel(const float* __restrict__ in, float* __restrict__ acc,
                              int relu_flag) {
    __shared__ float shm[64];
    int c = blockIdx.x, sl = blockIdx.y;
    float s = 0.f, s2 = 0.f;
    for (int i = threadIdx.x; i < 16*PIX; i += blockDim.x) {
        int b = sl*16 + (i >> 10), p = i & 1023;
        float v = in[(b*CH + c)*PIX + p];
        if (relu_flag) v = fmaxf(v, 0.f);
        s += v; s2 += v*v;
    }
    block_reduce_2(s, s2, shm);
    if (threadIdx.x == 0) {
        atomicAdd(&acc[c], s);
        atomicAdd(&acc[CH + c], s2);
    }
}

__global__ void bn_apply_kernel(const float* __restrict__ in, const float* __restrict__ acc,
                                const float* __restrict__ g, const float* __restrict__ bta,
                                float* __restrict__ out) {
    __shared__ float smu, srs;
    int idx = blockIdx.x*256 + threadIdx.x;
    int c = (idx >> 10) % CH;
    if (threadIdx.x == 0) {
        float m = acc[c] * (1.f/(BB*PIX));
        float var = acc[CH + c] * (1.f/(BB*PIX)) - m*m;
        smu = m; srs = rsqrtf(var + EPSV);
    }
    __syncthreads();
    if (idx >= BB*D) return;
    out[idx] = (in[idx] - smu) * srs * g[c] + bta[c];
}

// ---------------- conv1: 24->64 3x3 SAME + relu + gn1 stats (t1 bf16)
//   combine mode: z = sum(alpha_i F_i) computed on the fly, written to zout ----------------
__global__ void __launch_bounds__(512, 1)
conv1_kernel(const float* __restrict__ z, const float* __restrict__ Fb,
             const float* __restrict__ al, float* __restrict__ zout, int z_zero,
             const float* __restrict__ w, __nv_bfloat16* __restrict__ t1,
             float* __restrict__ s1o) {
    extern __shared__ float s[];
    float* ws = s + IN1;
    __shared__ float gs[8], gq[8];
    int b = blockIdx.x, tid = threadIdx.x;
    const size_t SLOT = (size_t)BB * D;
    pdl_launch_dependents();
    if (tid < 8) { gs[tid] = 0.f; gq[tid] = 0.f; }
    {
        float4 z4; z4.x=0.f; z4.y=0.f; z4.z=0.f; z4.w=0.f;
        float4* s4 = (float4*)s;
        for (int i = tid; i < IN1/4; i += 512) s4[i] = z4;
    }
    for (int i = tid; i < 64*24*3; i += 512) {
        int oc = i / 72, rem = i % 72, ic = rem / 3, ky = rem % 3;
        const float* src = w + (oc*24 + ic)*9 + ky*3;
        float* dst = ws + ((ic*3 + ky)*64 + oc)*4;
        dst[0] = src[0]; dst[1] = src[1]; dst[2] = src[2]; dst[3] = 0.f;
    }
    pdl_wait();
    __syncthreads();
    if (zout) {
        float a0=al[b*5+0], a1=al[b*5+1], a2=al[b*5+2], a3=al[b*5+3], a4=al[b*5+4];
        for (int task = tid; task < 768; task += 512) {
            int c = task >> 5, gr = task & 31;
            size_t off = (size_t)(b*24 + c)*PIX + gr*32;
            const float4* f0 = (const float4*)(Fb + off);
            const float4* f1 = (const float4*)(Fb + off + SLOT);
            const float4* f2 = (const float4*)(Fb + off + 2*SLOT);
            const float4* f3 = (const float4*)(Fb + off + 3*SLOT);
            const float4* f4 = (const float4*)(Fb + off + 4*SLOT);
            float4* zo = (float4*)(zout + off);
            float* dst = &s[c*(34*RS) + (gr+1)*RS + 1];
#pragma unroll
            for (int q = 0; q < 8; q++) {
                float4 v0=f0[q], v1=f1[q], v2=f2[q], v3=f3[q], v4=f4[q];
                float4 r;
                r.x = a0*v0.x + a1*v1.x + a2*v2.x + a3*v3.x + a4*v4.x;
                r.y = a0*v0.y + a1*v1.y + a2*v2.y + a3*v3.y + a4*v4.y;
                r.z = a0*v0.z + a1*v1.z + a2*v2.z + a3*v3.z + a4*v4.z;
                r.w = a0*v0.w + a1*v1.w + a2*v2.w + a3*v3.w + a4*v4.w;
                zo[q] = r;
                dst[q*4+0]=r.x; dst[q*4+1]=r.y; dst[q*4+2]=r.z; dst[q*4+3]=r.w;
            }
        }
    } else if (!z_zero) {
        for (int task = tid; task < 768; task += 512) {
            int c = task >> 5, gr = task & 31;
            size_t off = (size_t)(b*24 + c)*PIX + gr*32;
            const float4* zp = (const float4*)(z + off);
            float* dst = &s[c*(34*RS) + (gr+1)*RS + 1];
#pragma unroll
            for (int q = 0; q < 8; q++) {
                float4 v = zp[q];
                dst[q*4+0]=v.x; dst[q*4+1]=v.y; dst[q*4+2]=v.z; dst[q*4+3]=v.w;
            }
        }
    }
    __syncthreads();
    int ocg = tid >> 7;
    int t = tid & 127;
    int py = t >> 2, px0 = (t & 3) << 3;
    int lane = tid & 31;
#pragma unroll 1
    for (int tile = 0; tile < 2; tile++) {
        int oc0 = tile*32 + ocg*8;
        float acc[8][8];
#pragma unroll
        for (int j = 0; j < 8; j++)
#pragma unroll
            for (int p = 0; p < 8; p++) acc[j][p] = 0.f;
#pragma unroll 1
        for (int ic = 0; ic < 24; ic++)
#pragma unroll
            for (int ky = 0; ky < 3; ky++) {
                const float* row = &s[ic*(34*RS) + (py + ky)*RS + px0];
                float r[10];
#pragma unroll
                for (int p = 0; p < 10; p++) r[p] = row[p];
                const float4* wq4 = (const float4*)&ws[((ic*3 + ky)*64 + oc0)*4];
#pragma unroll
                for (int j = 0; j < 8; j++) {
                    float4 wv = wq4[j];
#pragma unroll
                    for (int p = 0; p < 8; p++)
                        acc[j][p] += r[p]*wv.x + r[p+1]*wv.y + r[p+2]*wv.z;
                }
            }
        float ss = 0.f, qq = 0.f;
#pragma unroll
        for (int j = 0; j < 8; j++) {
            float v[8];
#pragma unroll
            for (int p = 0; p < 8; p++) {
                v[p] = fmaxf(acc[j][p], 0.f);
                ss += v[p]; qq += v[p]*v[p];
            }
            *(uint4*)&t1[(size_t)(b*64 + oc0 + j)*PIX + py*32 + px0] = pack8_bf16(v);
        }
#pragma unroll
        for (int o = 16; o > 0; o >>= 1) {
            ss += __shfl_down_sync(0xffffffffu, ss, o);
            qq += __shfl_down_sync(0xffffffffu, qq, o);
        }
        if (lane == 0) {
            int grp = oc0 >> 3;
            atomicAdd(&gs[grp], ss);
            atomicAdd(&gq[grp], qq);
        }
    }
    __syncthreads();
    if (tid < 8) {
        float m = gs[tid] * (1.f/8192.f);
        float var = gq[tid] * (1.f/8192.f) - m*m;
        s1o[b*16 + tid*2]     = m;
        s1o[b*16 + tid*2 + 1] = rsqrtf(var + EPSV);
    }
}

// ---------------- conv2f: gn1-affine load (bf16 t1), conv 64->24 +xp, gn2 -> +z -> relu -> gn3,
//   writes F (fp32); if do_gram: G (bf16), Gram row slt, next alpha ----------------
__global__ void __launch_bounds__(512, 1)
conv2f_kernel(const __nv_bfloat16* __restrict__ t1, const float* __restrict__ w,
              const float* __restrict__ s1, const float* __restrict__ g1g,
              const float* __restrict__ g1b, const float* __restrict__ xp,
              const float* __restrict__ z,
              const float* __restrict__ g2g, const float* __restrict__ b2g,
              const float* __restrict__ g3g, const float* __restrict__ b3g,
              float* __restrict__ Fout, __nv_bfloat16* __restrict__ Gbuf,
              const __nv_bfloat16* __restrict__ Gall, int slt, float* __restrict__ Hb,
              int next_n, float* __restrict__ alpha, int do_gram) {
    extern __shared__ float s[];
    float* ws = s + IN2C;
    __shared__ float sc[64], bs[64];
    __shared__ float gs2[8], gq2[8], gs3[8], gq3[8];
    __shared__ float st2[16], st3[16];
    __shared__ float hd[MM];
    __shared__ float c2s[CH], c2b[CH], c3s[CH], c3b[CH];
    int b = blockIdx.x, tid = threadIdx.x;
    const size_t SLOT = (size_t)BB * D;
    pdl_launch_dependents();
    if (tid >= 64 && tid < 72) { gs2[tid-64]=0.f; gq2[tid-64]=0.f; gs3[tid-64]=0.f; gq3[tid-64]=0.f; }
    if (tid >= 96 && tid < 96+CH) {
        int c = tid - 96;
        c2s[c] = g2g[c]; c2b[c] = b2g[c];
        c3s[c] = g3g[c]; c3b[c] = b3g[c];
    }
    if (tid >= 128 && tid < 128+MM) hd[tid-128] = 0.f;
    {
        float4 z4; z4.x=0.f; z4.y=0.f; z4.z=0.f; z4.w=0.f;
        float4* s4 = (float4*)s;
        for (int i = tid; i < IN2C/4; i += 512) s4[i] = z4;
    }
    // chunk 0 weights repacked pre-wait
    for (int i = tid; i < 24*32*3; i += 512) {
        int oc = i / 96, rem = i % 96, ic = rem / 3, ky = rem % 3;
        const float* src = w + (oc*64 + ic)*9 + ky*3;
        float* dst = ws + ((ic*3 + ky)*24 + oc)*4;
        dst[0] = src[0]; dst[1] = src[1]; dst[2] = src[2]; dst[3] = 0.f;
    }
    pdl_wait();
    if (tid < 64) {
        int grp = tid >> 3;
        float m = s1[b*16 + grp*2], rs = s1[b*16 + grp*2 + 1];
        float gam = g1g[tid];
        sc[tid] = rs * gam;
        bs[tid] = g1b[tid] - m * rs * gam;
    }
    int ocg = tid >> 7, t = tid & 127;
    int py = t >> 2, px0 = (t & 3) << 3;
    int lane = tid & 31;
    float acc[6][8];
#pragma unroll
    for (int j = 0; j < 6; j++)
#pragma unroll
        for (int p = 0; p < 8; p++) acc[j][p] = 0.f;
#pragma unroll 1
    for (int chunk = 0; chunk < 2; chunk++) {
        __syncthreads();
        int icb = chunk * 32;
        if (chunk == 1) {
            for (int i = tid; i < 24*32*3; i += 512) {
                int oc = i / 96, rem = i % 96, ic = rem / 3, ky = rem % 3;
                const float* src = w + (oc*64 + 32 + ic)*9 + ky*3;
                float* dst = ws + ((ic*3 + ky)*24 + oc)*4;
                dst[0] = src[0]; dst[1] = src[1]; dst[2] = src[2]; dst[3] = 0.f;
            }
        }
        for (int task = tid; task < 1024; task += 512) {
            int c = task >> 5, gr = task & 31;
            int cg = icb + c;
            float scv = sc[cg], bsv = bs[cg];
            const uint4* tp = (const uint4*)(t1 + (size_t)(b*64 + cg)*PIX + gr*32);
            float* dst = &s[c*(34*RS) + (gr+1)*RS + 1];
#pragma unroll
            for (int q = 0; q < 4; q++) {
                float v[8];
                unpack8_bf16(tp[q], v);
#pragma unroll
                for (int e = 0; e < 8; e++)
                    dst[q*8 + e] = v[e]*scv + bsv;
            }
        }
        __syncthreads();
#pragma unroll 1
        for (int ic = 0; ic < 32; ic++)
#pragma unroll
            for (int ky = 0; ky < 3; ky++) {
                const float* row = &s[ic*(34*RS) + (py + ky)*RS + px0];
                float r[10];
#pragma unroll
                for (int p = 0; p < 10; p++) r[p] = row[p];
                const float4* wq4 = (const float4*)&ws[((ic*3 + ky)*24 + ocg*6)*4];
#pragma unroll
                for (int j = 0; j < 6; j++) {
                    float4 wv = wq4[j];
#pragma unroll
                    for (int p = 0; p < 8; p++)
                        acc[j][p] += r[p]*wv.x + r[p+1]*wv.y + r[p+2]*wv.z;
                }
            }
    }
    // ---- v = conv + xp ; gn2 stats ----
    float ss[2] = {0.f, 0.f}, qq[2] = {0.f, 0.f};
#pragma unroll
    for (int j = 0; j < 6; j++) {
        size_t idx = (size_t)(b*24 + ocg*6 + j)*PIX + py*32 + px0;
        float4 x0 = *(const float4*)&xp[idx];
        float4 x1 = *(const float4*)&xp[idx + 4];
        acc[j][0]+=x0.x; acc[j][1]+=x0.y; acc[j][2]+=x0.z; acc[j][3]+=x0.w;
        acc[j][4]+=x1.x; acc[j][5]+=x1.y; acc[j][6]+=x1.z; acc[j][7]+=x1.w;
        int u = j / 3;
        float sv = 0.f, qv = 0.f;
#pragma unroll
        for (int p = 0; p < 8; p++) { sv += acc[j][p]; qv += acc[j][p]*acc[j][p]; }
        ss[u] += sv; qq[u] += qv;
    }
#pragma unroll
    for (int o = 16; o > 0; o >>= 1)
#pragma unroll
        for (int u = 0; u < 2; u++) {
            ss[u] += __shfl_down_sync(0xffffffffu, ss[u], o);
            qq[u] += __shfl_down_sync(0xffffffffu, qq[u], o);
        }
    if (lane == 0)
#pragma unroll
        for (int u = 0; u < 2; u++) {
            atomicAdd(&gs2[ocg*2 + u], ss[u]);
            atomicAdd(&gq2[ocg*2 + u], qq[u]);
        }
    __syncthreads();
    if (tid < 8) {
        float m = gs2[tid] * (1.f/3072.f);
        st2[tid*2]   = m;
        st2[tid*2+1] = rsqrtf(gq2[tid] * (1.f/3072.f) - m*m + EPSV);
    }
    __syncthreads();
    // ---- w = relu(z + gn2affine(v)) ; gn3 stats ; cache z in smem ----
    float s3[2] = {0.f, 0.f}, q3[2] = {0.f, 0.f};
#pragma unroll
    for (int j = 0; j < 6; j++) {
        int c = ocg*6 + j;
        int grp = c / 3;
        float m1 = st2[grp*2], rs1 = st2[grp*2+1];
        float scl = rs1 * c2s[c];
        float off = c2b[c] - m1 * scl;
        size_t idx = (size_t)(b*24 + c)*PIX + py*32 + px0;
        float4 z0 = *(const float4*)&z[idx];
        float4 z1 = *(const float4*)&z[idx + 4];
        float* zs = &s[c*PIX + py*32 + px0];
        *(float4*)zs = z0; *(float4*)(zs + 4) = z1;
        float zv[8] = {z0.x,z0.y,z0.z,z0.w,z1.x,z1.y,z1.z,z1.w};
        int u = j / 3;
        float sv = 0.f, qv = 0.f;
#pragma unroll
        for (int p = 0; p < 8; p++) {
            float wv = fmaxf(zv[p] + acc[j][p]*scl + off, 0.f);
            acc[j][p] = wv;
            sv += wv; qv += wv*wv;
        }
        s3[u] += sv; q3[u] += qv;
    }
#pragma unroll
    for (int o = 16; o > 0; o >>= 1)
#pragma unroll
        for (int u = 0; u < 2; u++) {
            s3[u] += __shfl_down_sync(0xffffffffu, s3[u], o);
            q3[u] += __shfl_down_sync(0xffffffffu, q3[u], o);
        }
    if (lane == 0)
#pragma unroll
        for (int u = 0; u < 2; u++) {
            atomicAdd(&gs3[ocg*2 + u], s3[u]);
            atomicAdd(&gq3[ocg*2 + u], q3[u]);
        }
    __syncthreads();
    if (tid < 8) {
        float m = gs3[tid] * (1.f/3072.f);
        st3[tid*2]   = m;
        st3[tid*2+1] = rsqrtf(gq3[tid] * (1.f/3072.f) - m*m + EPSV);
    }
    __syncthreads();
    // ---- F = gn3affine(w); optionally G = F - z (bf16) + Gram row slt (z from smem) ----
    float dot[MM];
#pragma unroll
    for (int i = 0; i < MM; i++) dot[i] = 0.f;
#pragma unroll
    for (int j = 0; j < 6; j++) {
        int c = ocg*6 + j;
        int grp = c / 3;
        float m2 = st3[grp*2], rs2 = st3[grp*2+1];
        float scl = rs2 * c3s[c];
        float off = c3b[c] - m2 * scl;
        size_t idx = (size_t)(b*24 + c)*PIX + py*32 + px0;
        const float* zs = &s[c*PIX + py*32 + px0];
        float4 z0 = *(const float4*)zs;
        float4 z1 = *(const float4*)(zs + 4);
        float zv[8] = {z0.x,z0.y,z0.z,z0.w,z1.x,z1.y,z1.z,z1.w};
        float fv[8], gv[8];
#pragma unroll
        for (int p = 0; p < 8; p++) {
            fv[p] = acc[j][p]*scl + off;
            gv[p] = fv[p] - zv[p];
        }
        float4 f0; f0.x=fv[0]; f0.y=fv[1]; f0.z=fv[2]; f0.w=fv[3];
        float4 f1; f1.x=fv[4]; f1.y=fv[5]; f1.z=fv[6]; f1.w=fv[7];
        *(float4*)&Fout[idx] = f0; *(float4*)&Fout[idx + 4] = f1;
        if (do_gram) {
            *(uint4*)&Gbuf[idx] = pack8_bf16(gv);
#pragma unroll
            for (int i = 0; i < MM; i++) {
                if (i == slt) {
#pragma unroll
                    for (int p = 0; p < 8; p++) dot[i] += gv[p]*gv[p];
                } else {
                    uint4 u = *(const uint4*)(Gall + (size_t)i * SLOT + idx);
                    float gi[8];
                    unpack8_bf16(u, gi);
#pragma unroll
                    for (int p = 0; p < 8; p++) dot[i] += gv[p]*gi[p];
                }
            }
        }
    }
    if (do_gram) {
#pragma unroll
        for (int o = 16; o > 0; o >>= 1)
#pragma unroll
            for (int i = 0; i < MM; i++)
                dot[i] += __shfl_down_sync(0xffffffffu, dot[i], o);
        if (lane == 0)
#pragma unroll
            for (int i = 0; i < MM; i++) atomicAdd(&hd[i], dot[i]);
        __syncthreads();
        if (tid < MM) {
            float v = hd[tid];
            Hb[b*25 + slt*5 + tid] = v;
            Hb[b*25 + tid*5 + slt] = v;
        }
        __syncthreads();
        if (next_n > 0 && tid == 0) {
            int n = next_n, m = n + 1;
            float A[6][7];
            for (int i = 0; i < m; i++)
                for (int j = 0; j <= m; j++) A[i][j] = 0.f;
            for (int j = 1; j < m; j++) { A[0][j] = 1.f; A[j][0] = 1.f; }
            for (int i = 0; i < n; i++)
                for (int j = 0; j < n; j++) {
                    float hij = (i == slt) ? hd[j] : ((j == slt) ? hd[i] : Hb[b*25 + i*5 + j]);
                    A[i+1][j+1] = hij + ((i == j) ? LAMV : 0.f);
                }
            A[0][m] = 1.f;
            for (int col = 0; col < m; col++) {
                int piv = col; float best = fabsf(A[col][col]);
                for (int r = col + 1; r < m; r++) {
                    float v = fabsf(A[r][col]);
                    if (v > best) { best = v; piv = r; }
                }
                if (piv != col)
                    for (int j = col; j <= m; j++) { float tv = A[col][j]; A[col][j] = A[piv][j]; A[piv][j] = tv; }
                float inv = 1.f / A[col][col];
                for (int r = col + 1; r < m; r++) {
                    float f = A[r][col] * inv;
                    for (int j = col; j <= m; j++) A[r][j] -= f * A[col][j];
                }
            }
            float xs[6];
            for (int i = m - 1; i >= 0; i--) {
                float v = A[i][m];
                for (int j = i + 1; j < m; j++) v -= A[i][j] * xs[j];
                xs[i] = v / A[i][i];
            }
            for (int i = 0; i < 5; i++) alpha[b*5 + i] = (i < n) ? xs[i + 1] : 0.f;
        }
    }
}

// ---------------- post: relu -> BN apply (inline stats) -> 8x8 avgpool ----------------
__global__ void pool_kernel(const float* __restrict__ z, const float* __restrict__ acc,
                            const float* __restrict__ g, const float* __restrict__ bta,
                            float* __restrict__ pooled) {
    __shared__ float pl[16];
    __shared__ float smc, src_;
    int b = blockIdx.x / 24, c = blockIdx.x % 24;
    if (threadIdx.x < 16) pl[threadIdx.x] = 0.f;
    if (threadIdx.x == 0) {
        float m = acc[c] * (1.f/(BB*PIX));
        float var = acc[CH + c] * (1.f/(BB*PIX)) - m*m;
        smc = m; src_ = rsqrtf(var + EPSV);
    }
    __syncthreads();
    float mc = smc, rc = src_, gc = g[c], bc = bta[c];
    for (int i = threadIdx.x; i < 1024; i += 256) {
        int yy = i >> 5, xx = i & 31;
        float v = fmaxf(z[(b*24 + c)*PIX + i], 0.f);
        v = (v - mc) * rc * gc + bc;
        atomicAdd(&pl[(yy >> 3)*4 + (xx >> 3)], v);
    }
    __syncthreads();
    if (threadIdx.x < 16)
        pooled[(b*24 + c)*16 + threadIdx.x] = pl[threadIdx.x] * (1.f/64.f);
}

// ---------------- final FC ----------------
__global__ void fc_kernel(const float* __restrict__ pooled, const float* __restrict__ w,
                          const float* __restrict__ bias, float* __restrict__ out) {
    int b = blockIdx.x;
    int warp = threadIdx.x >> 5, lane = threadIdx.x & 31;
    float acc = 0.f;
    for (int k = lane; k < 384; k += 32)
        acc += pooled[b*384 + k] * w[warp*384 + k];
#pragma unroll
    for (int o = 16; o > 0; o >>= 1) acc += __shfl_down_sync(0xffffffffu, acc, o);
    if (lane == 0) out[b*10 + warp] = acc + bias[warp];
}

// ---------------- host orchestration ----------------
extern "C" void kernel_launch(void* const* d_in, const int* in_sizes, int n_in,
                              void* d_out, int out_size) {
    const float* x     = (const float*)d_in[0];
    const float* pw    = (const float*)d_in[1];
    const float* pbia  = (const float*)d_in[2];
    const float* pbn_g = (const float*)d_in[3];
    const float* pbn_b = (const float*)d_in[4];
    const float* w1    = (const float*)d_in[5];
    const float* g1g   = (const float*)d_in[6];
    const float* g1b   = (const float*)d_in[7];
    const float* w2    = (const float*)d_in[8];
    const float* g2g   = (const float*)d_in[9];
    const float* g2b   = (const float*)d_in[10];
    const float* g3g   = (const float*)d_in[11];
    const float* g3b   = (const float*)d_in[12];
    const float* qbn_g = (const float*)d_in[13];
    const float* qbn_b = (const float*)d_in[14];
    const float* fcw   = (const float*)d_in[15];
    const float* fcb   = (const float*)d_in[16];
    float* out = (float*)d_out;

    static bool attr_done = false;
    if (!attr_done) {
        cudaFuncSetAttribute(conv1_kernel,  cudaFuncAttributeMaxDynamicSharedMemorySize, SMEM1);
        cudaFuncSetAttribute(conv2f_kernel, cudaFuncAttributeMaxDynamicSharedMemorySize, SMEM2);
        attr_done = true;
    }

    float *zb, *Fb, *xp, *pre, *Hb, *al, *s1, *ac1, *ac2, *pl;
    __nv_bfloat16 *Gb, *t1;
    cudaGetSymbolAddress((void**)&zb,  g_z);
    cudaGetSymbolAddress((void**)&Fb,  g_F);
    cudaGetSymbolAddress((void**)&Gb,  g_G);
    cudaGetSymbolAddress((void**)&xp,  g_xp);
    cudaGetSymbolAddress((void**)&pre, g_pre);
    cudaGetSymbolAddress((void**)&t1,  g_t1);
    cudaGetSymbolAddress((void**)&Hb,  g_H);
    cudaGetSymbolAddress((void**)&al,  g_al);
    cudaGetSymbolAddress((void**)&s1,  g_s1);
    cudaGetSymbolAddress((void**)&ac1, g_acc1);
    cudaGetSymbolAddress((void**)&ac2, g_acc2);
    cudaGetSymbolAddress((void**)&pl,  g_pool);

    const size_t SLOT = (size_t)BB * D;

    cudaMemsetAsync(ac1, 0, 2*CH*sizeof(float));
    cudaMemsetAsync(ac2, 0, 2*CH*sizeof(float));
    cudaMemsetAsync(zb, 0, SLOT * sizeof(float));     // z=0 for iteration 0 (conv2f reads it)

    preconv_kernel<<<128, 256>>>(x, pw, pbia, pre);
    bn_acc_kernel<<<dim3(24, 8), 256>>>(pre, ac1, 0);
    bn_apply_kernel<<<(BB*D + 255)/256, 256>>>(pre, ac1, pbn_g, pbn_b, xp);

    cudaLaunchAttribute pdl_attr[1];
    pdl_attr[0].id = cudaLaunchAttributeProgrammaticStreamSerialization;
    pdl_attr[0].val.programmaticStreamSerializationAllowed = 1;

    auto launch_conv1 = [&](const float* zptr, bool combine, int z_zero) {
        cudaLaunchConfig_t cfg = {};
        cfg.gridDim = dim3(128, 1, 1);
        cfg.blockDim = dim3(512, 1, 1);
        cfg.dynamicSmemBytes = SMEM1;
        cfg.stream = 0;
        cfg.attrs = pdl_attr;
        cfg.numAttrs = 1;
        cudaLaunchKernelEx(&cfg, conv1_kernel,
                           zptr, (const float*)Fb, (const float*)al,
                           combine ? zb : (float*)nullptr, z_zero,
                           w1, t1, s1);
    };
    auto launch_conv2f = [&](const float* zptr, int slt, int next_n, int do_gram) {
        cudaLaunchConfig_t cfg = {};
        cfg.gridDim = dim3(128, 1, 1);
        cfg.blockDim = dim3(512, 1, 1);
        cfg.dynamicSmemBytes = SMEM2;
        cfg.stream = 0;
        cfg.attrs = pdl_attr;
        cfg.numAttrs = 1;
        cudaLaunchKernelEx(&cfg, conv2f_kernel,
                           (const __nv_bfloat16*)t1, w2, (const float*)s1, g1g, g1b,
                           (const float*)xp, zptr,
                           g2g, g2b, g3g, g3b,
                           Fb + (size_t)slt*SLOT, Gb + (size_t)slt*SLOT,
                           (const __nv_bfloat16*)Gb, slt, Hb, next_n, al, do_gram);
    };

    // iter 0: z = 0 (conv1 skips fill; conv2f reads memset zb)  ->  F0 (slot 0)
    launch_conv1(zb, false, 1);
    launch_conv2f(zb, 0, 0, 1);
    // iter 1: z = F0 read in place (no memcpy)  ->  F1 (slot 1); alpha for k=2
    launch_conv1(Fb, false, 0);
    launch_conv2f(Fb, 1, 2, 1);

    for (int k = 2; k < 25; k++) {
        int nn = (k + 1 < 5) ? (k + 1) : 5;
        launch_conv1(zb, true, 0);                       // conv1 builds z into zb
        launch_conv2f(zb, k % 5, (k < 24) ? nn : 0, (k < 24) ? 1 : 0);
    }

    const float* zf = Fb + 4 * SLOT;   // z = f(z_star) = F[:,4]

    bn_acc_kernel<<<dim3(24, 8), 256>>>(zf, ac2, 1);
    pool_kernel<<<128*24, 256>>>(zf, ac2, qbn_g, qbn_b, pl);
    fc_kernel<<<128, 320>>>(pl, fcw, fcb, out);
}